// round 1
// baseline (speedup 1.0000x reference)
#include <cuda_runtime.h>
#include <math.h>
#include <stdint.h>

// Problem dims
#define V_ 32000
#define E_ 1024
#define H_ 1024
#define A_ 10
#define S_ 512
#define B_ 64

// Scratch layout (floats) in one __device__ buffer (no allocations allowed)
#define OFF_HWA1 0            // B*A = 640
#define OFF_E    1024         // S*B = 32768
#define OFF_C    36864        // B*H = 65536
#define OFF_XC   102400       // B*(E+H) = 131072
#define OFF_GIP  233472       // 4*B*3H = 786432
#define OFF_GHP  1019904      // 2*B*3H = 393216
#define SCRATCH_FLOATS 1413120

__device__ float g_scratch[SCRATCH_FLOATS];

// ---------------------------------------------------------------------------
// hWa1[b][a] = sum_h h_last[b,h] * Wa1[a,h]   (first-half columns of Wa1)
// grid(B), block(256)
// ---------------------------------------------------------------------------
__global__ __launch_bounds__(256) void k_hWa1(const float* __restrict__ h,
                                              const float* __restrict__ Wa1,
                                              float* __restrict__ hWa1)
{
    const int b = blockIdx.x;
    const int tid = threadIdx.x;
    float4 hv = ((const float4*)(h + (size_t)b * H_))[tid];
    float p[A_];
#pragma unroll
    for (int a = 0; a < A_; a++) {
        float4 w = ((const float4*)(Wa1 + (size_t)a * (2 * H_)))[tid];
        p[a] = hv.x * w.x + hv.y * w.y + hv.z * w.z + hv.w * w.w;
    }
    __shared__ float red[8][A_];
    const int lane = tid & 31, wid = tid >> 5;
#pragma unroll
    for (int a = 0; a < A_; a++) {
        float v = p[a];
        v += __shfl_xor_sync(0xffffffffu, v, 16);
        v += __shfl_xor_sync(0xffffffffu, v, 8);
        v += __shfl_xor_sync(0xffffffffu, v, 4);
        v += __shfl_xor_sync(0xffffffffu, v, 2);
        v += __shfl_xor_sync(0xffffffffu, v, 1);
        if (lane == 0) red[wid][a] = v;
    }
    __syncthreads();
    if (tid < A_) {
        float s = 0.f;
#pragma unroll
        for (int w = 0; w < 8; w++) s += red[w][tid];
        hWa1[b * A_ + tid] = s;
    }
}

// ---------------------------------------------------------------------------
// scores: e[r] (r = s*B+b) = sum_a Wa2[a]*tanh(hWa1[b][a] + enc[r,:].Wa1[a,H:])
// grid(S*B/32), block(256): 8 warps x 4 rows/warp. Wa1 second half in smem.
// ---------------------------------------------------------------------------
__global__ __launch_bounds__(256) void k_scores(const float* __restrict__ enc,
                                                const float* __restrict__ Wa1,
                                                const float* __restrict__ Wa2,
                                                const float* __restrict__ hWa1,
                                                float* __restrict__ e_out)
{
    __shared__ float Wsh[A_ * H_];   // 40KB
    const int tid = threadIdx.x;
    // load Wa1[:, H:2H] into smem (f4)
    for (int id = tid; id < A_ * (H_ / 4); id += 256) {
        int a = id >> 8;          // id / 256
        int c4 = id & 255;
        ((float4*)Wsh)[a * 256 + c4] =
            *(const float4*)(Wa1 + (size_t)a * (2 * H_) + H_ + (c4 << 2));
    }
    __syncthreads();

    const int lane = tid & 31, wid = tid >> 5;
    const size_t r0 = (size_t)blockIdx.x * 32 + wid * 4;
    const float4* e4 = (const float4*)enc;

    float acc0[A_], acc1[A_], acc2[A_], acc3[A_];
#pragma unroll
    for (int a = 0; a < A_; a++) { acc0[a] = 0.f; acc1[a] = 0.f; acc2[a] = 0.f; acc3[a] = 0.f; }

#pragma unroll
    for (int it = 0; it < 8; it++) {
        const int h4 = it * 32 + lane;
        float4 x0 = e4[(r0 + 0) * 256 + h4];
        float4 x1 = e4[(r0 + 1) * 256 + h4];
        float4 x2 = e4[(r0 + 2) * 256 + h4];
        float4 x3 = e4[(r0 + 3) * 256 + h4];
#pragma unroll
        for (int a = 0; a < A_; a++) {
            float4 w = ((const float4*)Wsh)[a * 256 + h4];
            acc0[a] += x0.x * w.x + x0.y * w.y + x0.z * w.z + x0.w * w.w;
            acc1[a] += x1.x * w.x + x1.y * w.y + x1.z * w.z + x1.w * w.w;
            acc2[a] += x2.x * w.x + x2.y * w.y + x2.z * w.z + x2.w * w.w;
            acc3[a] += x3.x * w.x + x3.y * w.y + x3.z * w.z + x3.w * w.w;
        }
    }
    // butterfly reduce each accumulator across the warp
#pragma unroll
    for (int a = 0; a < A_; a++) {
        float v;
        v = acc0[a];
        v += __shfl_xor_sync(0xffffffffu, v, 16); v += __shfl_xor_sync(0xffffffffu, v, 8);
        v += __shfl_xor_sync(0xffffffffu, v, 4);  v += __shfl_xor_sync(0xffffffffu, v, 2);
        v += __shfl_xor_sync(0xffffffffu, v, 1);  acc0[a] = v;
        v = acc1[a];
        v += __shfl_xor_sync(0xffffffffu, v, 16); v += __shfl_xor_sync(0xffffffffu, v, 8);
        v += __shfl_xor_sync(0xffffffffu, v, 4);  v += __shfl_xor_sync(0xffffffffu, v, 2);
        v += __shfl_xor_sync(0xffffffffu, v, 1);  acc1[a] = v;
        v = acc2[a];
        v += __shfl_xor_sync(0xffffffffu, v, 16); v += __shfl_xor_sync(0xffffffffu, v, 8);
        v += __shfl_xor_sync(0xffffffffu, v, 4);  v += __shfl_xor_sync(0xffffffffu, v, 2);
        v += __shfl_xor_sync(0xffffffffu, v, 1);  acc2[a] = v;
        v = acc3[a];
        v += __shfl_xor_sync(0xffffffffu, v, 16); v += __shfl_xor_sync(0xffffffffu, v, 8);
        v += __shfl_xor_sync(0xffffffffu, v, 4);  v += __shfl_xor_sync(0xffffffffu, v, 2);
        v += __shfl_xor_sync(0xffffffffu, v, 1);  acc3[a] = v;
    }
    // lanes 0..3 finish one row each (static register selection)
    float tsum[A_];
#pragma unroll
    for (int a = 0; a < A_; a++) {
        float t = acc0[a];
        if (lane == 1) t = acc1[a];
        if (lane == 2) t = acc2[a];
        if (lane == 3) t = acc3[a];
        tsum[a] = t;
    }
    if (lane < 4) {
        const size_t r = r0 + lane;
        const int b = (int)(r & (B_ - 1));
        float ev = 0.f;
#pragma unroll
        for (int a = 0; a < A_; a++)
            ev += Wa2[a] * tanhf(hWa1[b * A_ + a] + tsum[a]);
        e_out[r] = ev;
    }
}

// ---------------------------------------------------------------------------
// softmax over s (axis 0) per b, in place. grid(B), block(256), 2 vals/thread
// ---------------------------------------------------------------------------
__global__ __launch_bounds__(256) void k_softmax(float* __restrict__ e)
{
    const int b = blockIdx.x, tid = threadIdx.x;
    __shared__ float red[256];
    float v0 = e[(size_t)tid * B_ + b];
    float v1 = e[(size_t)(tid + 256) * B_ + b];
    red[tid] = fmaxf(v0, v1);
    __syncthreads();
    for (int s = 128; s > 0; s >>= 1) {
        if (tid < s) red[tid] = fmaxf(red[tid], red[tid + s]);
        __syncthreads();
    }
    const float M = red[0];
    __syncthreads();
    float e0 = expf(v0 - M), e1 = expf(v1 - M);
    red[tid] = e0 + e1;
    __syncthreads();
    for (int s = 128; s > 0; s >>= 1) {
        if (tid < s) red[tid] += red[tid + s];
        __syncthreads();
    }
    const float inv = 1.f / red[0];
    e[(size_t)tid * B_ + b] = e0 * inv;
    e[(size_t)(tid + 256) * B_ + b] = e1 * inv;
}

// ---------------------------------------------------------------------------
// context: c[b,h] = sum_s alpha[s,b] * enc[s,b,h]
// grid(4, B), block(128): thread handles float2 of h
// ---------------------------------------------------------------------------
__global__ __launch_bounds__(128) void k_context(const float* __restrict__ alpha,
                                                 const float* __restrict__ enc,
                                                 float* __restrict__ c)
{
    const int b = blockIdx.y;
    const int h0 = blockIdx.x * 256 + threadIdx.x * 2;
    __shared__ float al[S_];
    for (int s = threadIdx.x; s < S_; s += 128) al[s] = alpha[(size_t)s * B_ + b];
    __syncthreads();
    float ax = 0.f, ay = 0.f;
    const float* base = enc + (size_t)b * H_ + h0;
#pragma unroll 4
    for (int s = 0; s < S_; s++) {
        float2 v = *(const float2*)(base + (size_t)s * (B_ * H_));
        float a = al[s];
        ax += a * v.x;
        ay += a * v.y;
    }
    *(float2*)(c + (size_t)b * H_ + h0) = make_float2(ax, ay);
}

// ---------------------------------------------------------------------------
// xc[b,:] = [ emb[tok[b], :E] ; c[b, :H] ]   grid(B), block(256)
// ---------------------------------------------------------------------------
__global__ __launch_bounds__(256) void k_xc(const int* __restrict__ tok,
                                            const float* __restrict__ emb,
                                            const float* __restrict__ c,
                                            float* __restrict__ xc)
{
    const int b = blockIdx.x, t = threadIdx.x;
    const int tk = tok[b];
    float4* x4 = (float4*)(xc + (size_t)b * (E_ + H_));
    x4[t]       = ((const float4*)(emb + (size_t)tk * E_))[t];
    x4[256 + t] = ((const float4*)(c + (size_t)b * H_))[t];
}

// ---------------------------------------------------------------------------
// GEMM: C[b, n] = A[b, :K] . W[n, :K] (+bias), 64 rows, N = gridDim.x*64.
// blockIdx.y = K-split index; output row = blockIdx.y*64 + b (partials).
// block(128): 16(tx) x 8(ty) threads, each 8b x 4n register tile.
// smem tiles stored k-major with +1 pad per 32 floats (conflict-free).
// ---------------------------------------------------------------------------
__global__ __launch_bounds__(128) void k_gemm64(const float* __restrict__ A,
                                                const float* __restrict__ W,
                                                const float* __restrict__ bias,
                                                float* __restrict__ C,
                                                int K, int ldc, int klen)
{
    __shared__ float As[32 * 66];
    __shared__ float Ws[32 * 66];
    const int tid = threadIdx.x;
    const int tx = tid & 15;          // n-group (4 n each)
    const int ty = tid >> 4;          // b-group (8 b each)
    const int n0 = blockIdx.x * 64;
    const int kbase = blockIdx.y * klen;
    const int aoff = ty * 8 + (ty >= 4 ? 1 : 0);
    const int woff = tx * 4 + (tx >= 8 ? 1 : 0);

    float acc[8][4];
#pragma unroll
    for (int i = 0; i < 8; i++)
#pragma unroll
        for (int j = 0; j < 4; j++) acc[i][j] = 0.f;

    for (int kc = 0; kc < klen; kc += 32) {
        __syncthreads();
#pragma unroll
        for (int p = 0; p < 4; p++) {
            const int id = tid + p * 128;
            const int row = id >> 3;
            const int c4 = (id & 7) << 2;
            const int roff = row + (row >> 5);
            float4 av = *(const float4*)(A + (size_t)row * K + kbase + kc + c4);
            As[(c4 + 0) * 66 + roff] = av.x;
            As[(c4 + 1) * 66 + roff] = av.y;
            As[(c4 + 2) * 66 + roff] = av.z;
            As[(c4 + 3) * 66 + roff] = av.w;
            float4 wv = *(const float4*)(W + (size_t)(n0 + row) * K + kbase + kc + c4);
            Ws[(c4 + 0) * 66 + roff] = wv.x;
            Ws[(c4 + 1) * 66 + roff] = wv.y;
            Ws[(c4 + 2) * 66 + roff] = wv.z;
            Ws[(c4 + 3) * 66 + roff] = wv.w;
        }
        __syncthreads();
#pragma unroll 8
        for (int kk = 0; kk < 32; kk++) {
            const float w0 = Ws[kk * 66 + woff + 0];
            const float w1 = Ws[kk * 66 + woff + 1];
            const float w2 = Ws[kk * 66 + woff + 2];
            const float w3 = Ws[kk * 66 + woff + 3];
#pragma unroll
            for (int i = 0; i < 8; i++) {
                const float a = As[kk * 66 + aoff + i];
                acc[i][0] += a * w0;
                acc[i][1] += a * w1;
                acc[i][2] += a * w2;
                acc[i][3] += a * w3;
            }
        }
    }
    float b0 = 0.f, b1 = 0.f, b2 = 0.f, b3 = 0.f;
    if (bias) {
        b0 = bias[n0 + tx * 4 + 0];
        b1 = bias[n0 + tx * 4 + 1];
        b2 = bias[n0 + tx * 4 + 2];
        b3 = bias[n0 + tx * 4 + 3];
    }
#pragma unroll
    for (int i = 0; i < 8; i++) {
        const size_t brow = (size_t)(blockIdx.y * 64 + ty * 8 + i);
        float4 o = make_float4(acc[i][0] + b0, acc[i][1] + b1, acc[i][2] + b2, acc[i][3] + b3);
        *(float4*)(C + brow * ldc + n0 + tx * 4) = o;
    }
}

// ---------------------------------------------------------------------------
// gates: merge K-split partials, apply GRU nonlinearity, write h_new
// grid(B*H/256), block(256)
// ---------------------------------------------------------------------------
__global__ __launch_bounds__(256) void k_gates(const float* __restrict__ gip,
                                               const float* __restrict__ ghp,
                                               const float* __restrict__ b_ih,
                                               const float* __restrict__ b_hh,
                                               const float* __restrict__ h_last,
                                               float* __restrict__ h_new)
{
    const int idx = blockIdx.x * blockDim.x + threadIdx.x;  // 0..B*H-1
    const int b = idx >> 10;
    const int h = idx & 1023;
    float ir = 0.f, iz = 0.f, in_ = 0.f;
#pragma unroll
    for (int sp = 0; sp < 4; sp++) {
        const float* g = gip + (size_t)(sp * B_ + b) * (3 * H_);
        ir += g[h];
        iz += g[h + H_];
        in_ += g[h + 2 * H_];
    }
    float hr = 0.f, hz = 0.f, hn = 0.f;
#pragma unroll
    for (int sp = 0; sp < 2; sp++) {
        const float* g = ghp + (size_t)(sp * B_ + b) * (3 * H_);
        hr += g[h];
        hz += g[h + H_];
        hn += g[h + 2 * H_];
    }
    ir += b_ih[h];        hr += b_hh[h];
    iz += b_ih[h + H_];   hz += b_hh[h + H_];
    in_ += b_ih[h + 2 * H_]; hn += b_hh[h + 2 * H_];
    const float r = 1.f / (1.f + expf(-(ir + hr)));
    const float z = 1.f / (1.f + expf(-(iz + hz)));
    const float n = tanhf(in_ + r * hn);
    h_new[idx] = (1.f - z) * n + z * h_last[idx];
}

// ---------------------------------------------------------------------------
extern "C" void kernel_launch(void* const* d_in, const int* in_sizes, int n_in,
                              void* d_out, int out_size)
{
    (void)in_sizes; (void)n_in; (void)out_size;
    const int* dec_input = (const int*)d_in[0];
    const float* dec_hidden = (const float*)d_in[1];   // (1,B,H) == (B,H)
    const float* enc = (const float*)d_in[2];          // (S,B,H)
    const float* emb = (const float*)d_in[3];          // (V,E)
    const float* Wa1 = (const float*)d_in[4];          // (A,2H)
    const float* Wa2 = (const float*)d_in[5];          // (1,A)
    const float* W_ih = (const float*)d_in[6];         // (3H, E+H)
    const float* W_hh = (const float*)d_in[7];         // (3H, H)
    const float* b_ih = (const float*)d_in[8];
    const float* b_hh = (const float*)d_in[9];
    const float* W_out = (const float*)d_in[10];       // (V,H)
    const float* b_out = (const float*)d_in[11];

    float* out = (float*)d_out;
    float* logits = out;                          // B*V
    float* h_new = out + (size_t)B_ * V_;         // B*H

    float* scratch = nullptr;
    cudaGetSymbolAddress((void**)&scratch, g_scratch);
    float* hWa1 = scratch + OFF_HWA1;
    float* e = scratch + OFF_E;
    float* c = scratch + OFF_C;
    float* xc = scratch + OFF_XC;
    float* gip = scratch + OFF_GIP;
    float* ghp = scratch + OFF_GHP;

    // attention
    k_hWa1<<<B_, 256>>>(dec_hidden, Wa1, hWa1);
    k_scores<<<(S_ * B_) / 32, 256>>>(enc, Wa1, Wa2, hWa1, e);
    k_softmax<<<B_, 256>>>(e);
    k_context<<<dim3(4, B_), 128>>>(e, enc, c);

    // GRU inputs
    k_xc<<<B_, 256>>>(dec_input, emb, c, xc);
    // gh partials: K=1024, split 2
    k_gemm64<<<dim3(48, 2), 128>>>(dec_hidden, W_hh, nullptr, ghp, H_, 3 * H_, 512);
    // gi partials: K=2048, split 4
    k_gemm64<<<dim3(48, 4), 128>>>(xc, W_ih, nullptr, gip, E_ + H_, 3 * H_, 512);
    // gates -> h_new (written directly into output tail)
    k_gates<<<(B_ * H_) / 256, 256>>>(gip, ghp, b_ih, b_hh, dec_hidden, h_new);

    // logits = h_new @ W_out.T + b_out
    k_gemm64<<<dim3(V_ / 64, 1), 128>>>(h_new, W_out, b_out, logits, H_, V_, H_);
}

// round 2
// speedup vs baseline: 1.2945x; 1.2945x over previous
#include <cuda_runtime.h>
#include <math.h>
#include <stdint.h>

// Problem dims
#define V_ 32000
#define E_ 1024
#define H_ 1024
#define A_ 10
#define S_ 512
#define B_ 64

#define NSPLIT 8

// Scratch layout (floats)
#define OFF_HWA1 0            // B*A = 640
#define OFF_E    1024         // S*B = 32768
#define OFF_C    36864        // B*H = 65536
#define OFF_XC   102400       // B*(E+H) = 131072
#define OFF_GIP  233472       // 4*B*3H = 786432
#define OFF_GHP  1019904      // 2*B*3H = 393216
#define OFF_CP   1413120      // NSPLIT*B*H = 524288
#define SCRATCH_FLOATS 1937408

__device__ float g_scratch[SCRATCH_FLOATS];

// ---------------------------------------------------------------------------
// hWa1[b][a] = sum_h h_last[b,h] * Wa1[a,h]
// ---------------------------------------------------------------------------
__global__ __launch_bounds__(256) void k_hWa1(const float* __restrict__ h,
                                              const float* __restrict__ Wa1,
                                              float* __restrict__ hWa1)
{
    const int b = blockIdx.x;
    const int tid = threadIdx.x;
    float4 hv = ((const float4*)(h + (size_t)b * H_))[tid];
    float p[A_];
#pragma unroll
    for (int a = 0; a < A_; a++) {
        float4 w = ((const float4*)(Wa1 + (size_t)a * (2 * H_)))[tid];
        p[a] = hv.x * w.x + hv.y * w.y + hv.z * w.z + hv.w * w.w;
    }
    __shared__ float red[8][A_];
    const int lane = tid & 31, wid = tid >> 5;
#pragma unroll
    for (int a = 0; a < A_; a++) {
        float v = p[a];
        v += __shfl_xor_sync(0xffffffffu, v, 16);
        v += __shfl_xor_sync(0xffffffffu, v, 8);
        v += __shfl_xor_sync(0xffffffffu, v, 4);
        v += __shfl_xor_sync(0xffffffffu, v, 2);
        v += __shfl_xor_sync(0xffffffffu, v, 1);
        if (lane == 0) red[wid][a] = v;
    }
    __syncthreads();
    if (tid < A_) {
        float s = 0.f;
#pragma unroll
        for (int w = 0; w < 8; w++) s += red[w][tid];
        hWa1[b * A_ + tid] = s;
    }
}

// ---------------------------------------------------------------------------
// scores: e[r] = sum_a Wa2[a]*tanh(hWa1[b][a] + enc[r,:].Wa1[a,H:])
// ---------------------------------------------------------------------------
__global__ __launch_bounds__(256) void k_scores(const float* __restrict__ enc,
                                                const float* __restrict__ Wa1,
                                                const float* __restrict__ Wa2,
                                                const float* __restrict__ hWa1,
                                                float* __restrict__ e_out)
{
    __shared__ float Wsh[A_ * H_];   // 40KB
    const int tid = threadIdx.x;
    for (int id = tid; id < A_ * (H_ / 4); id += 256) {
        int a = id >> 8;
        int c4 = id & 255;
        ((float4*)Wsh)[a * 256 + c4] =
            *(const float4*)(Wa1 + (size_t)a * (2 * H_) + H_ + (c4 << 2));
    }
    __syncthreads();

    const int lane = tid & 31, wid = tid >> 5;
    const size_t r0 = (size_t)blockIdx.x * 32 + wid * 4;
    const float4* e4 = (const float4*)enc;

    float acc0[A_], acc1[A_], acc2[A_], acc3[A_];
#pragma unroll
    for (int a = 0; a < A_; a++) { acc0[a] = 0.f; acc1[a] = 0.f; acc2[a] = 0.f; acc3[a] = 0.f; }

#pragma unroll
    for (int it = 0; it < 8; it++) {
        const int h4 = it * 32 + lane;
        float4 x0 = e4[(r0 + 0) * 256 + h4];
        float4 x1 = e4[(r0 + 1) * 256 + h4];
        float4 x2 = e4[(r0 + 2) * 256 + h4];
        float4 x3 = e4[(r0 + 3) * 256 + h4];
#pragma unroll
        for (int a = 0; a < A_; a++) {
            float4 w = ((const float4*)Wsh)[a * 256 + h4];
            acc0[a] += x0.x * w.x + x0.y * w.y + x0.z * w.z + x0.w * w.w;
            acc1[a] += x1.x * w.x + x1.y * w.y + x1.z * w.z + x1.w * w.w;
            acc2[a] += x2.x * w.x + x2.y * w.y + x2.z * w.z + x2.w * w.w;
            acc3[a] += x3.x * w.x + x3.y * w.y + x3.z * w.z + x3.w * w.w;
        }
    }
#pragma unroll
    for (int a = 0; a < A_; a++) {
        float v;
        v = acc0[a];
        v += __shfl_xor_sync(0xffffffffu, v, 16); v += __shfl_xor_sync(0xffffffffu, v, 8);
        v += __shfl_xor_sync(0xffffffffu, v, 4);  v += __shfl_xor_sync(0xffffffffu, v, 2);
        v += __shfl_xor_sync(0xffffffffu, v, 1);  acc0[a] = v;
        v = acc1[a];
        v += __shfl_xor_sync(0xffffffffu, v, 16); v += __shfl_xor_sync(0xffffffffu, v, 8);
        v += __shfl_xor_sync(0xffffffffu, v, 4);  v += __shfl_xor_sync(0xffffffffu, v, 2);
        v += __shfl_xor_sync(0xffffffffu, v, 1);  acc1[a] = v;
        v = acc2[a];
        v += __shfl_xor_sync(0xffffffffu, v, 16); v += __shfl_xor_sync(0xffffffffu, v, 8);
        v += __shfl_xor_sync(0xffffffffu, v, 4);  v += __shfl_xor_sync(0xffffffffu, v, 2);
        v += __shfl_xor_sync(0xffffffffu, v, 1);  acc2[a] = v;
        v = acc3[a];
        v += __shfl_xor_sync(0xffffffffu, v, 16); v += __shfl_xor_sync(0xffffffffu, v, 8);
        v += __shfl_xor_sync(0xffffffffu, v, 4);  v += __shfl_xor_sync(0xffffffffu, v, 2);
        v += __shfl_xor_sync(0xffffffffu, v, 1);  acc3[a] = v;
    }
    float tsum[A_];
#pragma unroll
    for (int a = 0; a < A_; a++) {
        float t = acc0[a];
        if (lane == 1) t = acc1[a];
        if (lane == 2) t = acc2[a];
        if (lane == 3) t = acc3[a];
        tsum[a] = t;
    }
    if (lane < 4) {
        const size_t r = r0 + lane;
        const int b = (int)(r & (B_ - 1));
        float ev = 0.f;
#pragma unroll
        for (int a = 0; a < A_; a++)
            ev += Wa2[a] * tanhf(hWa1[b * A_ + a] + tsum[a]);
        e_out[r] = ev;
    }
}

// ---------------------------------------------------------------------------
// softmax over s (axis 0) per b, in place
// ---------------------------------------------------------------------------
__global__ __launch_bounds__(256) void k_softmax(float* __restrict__ e)
{
    const int b = blockIdx.x, tid = threadIdx.x;
    __shared__ float red[256];
    float v0 = e[(size_t)tid * B_ + b];
    float v1 = e[(size_t)(tid + 256) * B_ + b];
    red[tid] = fmaxf(v0, v1);
    __syncthreads();
    for (int s = 128; s > 0; s >>= 1) {
        if (tid < s) red[tid] = fmaxf(red[tid], red[tid + s]);
        __syncthreads();
    }
    const float M = red[0];
    __syncthreads();
    float e0 = expf(v0 - M), e1 = expf(v1 - M);
    red[tid] = e0 + e1;
    __syncthreads();
    for (int s = 128; s > 0; s >>= 1) {
        if (tid < s) red[tid] += red[tid + s];
        __syncthreads();
    }
    const float inv = 1.f / red[0];
    e[(size_t)tid * B_ + b] = e0 * inv;
    e[(size_t)(tid + 256) * B_ + b] = e1 * inv;
}

// ---------------------------------------------------------------------------
// context partials: cp[sp][b][h] = sum_{s in split sp} alpha[s,b]*enc[s,b,h]
// grid(2, B, NSPLIT), block(128): thread handles float4 of h, 64 s-iters
// ---------------------------------------------------------------------------
__global__ __launch_bounds__(128) void k_context_part(const float* __restrict__ alpha,
                                                      const float* __restrict__ enc,
                                                      float* __restrict__ cp)
{
    const int b = blockIdx.y;
    const int sp = blockIdx.z;
    const int h0 = blockIdx.x * 512 + threadIdx.x * 4;
    __shared__ float al[S_ / NSPLIT];
    if (threadIdx.x < S_ / NSPLIT)
        al[threadIdx.x] = alpha[(size_t)(sp * (S_ / NSPLIT) + threadIdx.x) * B_ + b];
    __syncthreads();
    float4 acc = make_float4(0.f, 0.f, 0.f, 0.f);
    const float* base = enc + (size_t)(sp * (S_ / NSPLIT)) * B_ * H_ + (size_t)b * H_ + h0;
#pragma unroll 4
    for (int s = 0; s < S_ / NSPLIT; s++) {
        float4 v = *(const float4*)(base + (size_t)s * (B_ * H_));
        float a = al[s];
        acc.x += a * v.x; acc.y += a * v.y; acc.z += a * v.z; acc.w += a * v.w;
    }
    *(float4*)(cp + ((size_t)sp * B_ + b) * H_ + h0) = acc;
}

// ---------------------------------------------------------------------------
// reduce context partials: c = sum_sp cp[sp]
// grid(64), block(256): one float4 per thread
// ---------------------------------------------------------------------------
__global__ __launch_bounds__(256) void k_context_reduce(const float* __restrict__ cp,
                                                        float* __restrict__ c)
{
    const int idx = blockIdx.x * 256 + threadIdx.x;  // 0 .. B*H/4-1
    float4 acc = make_float4(0.f, 0.f, 0.f, 0.f);
#pragma unroll
    for (int sp = 0; sp < NSPLIT; sp++) {
        float4 v = ((const float4*)cp)[(size_t)sp * (B_ * H_ / 4) + idx];
        acc.x += v.x; acc.y += v.y; acc.z += v.z; acc.w += v.w;
    }
    ((float4*)c)[idx] = acc;
}

// ---------------------------------------------------------------------------
// xc[b,:] = [ emb[tok[b], :E] ; c[b, :H] ]
// ---------------------------------------------------------------------------
__global__ __launch_bounds__(256) void k_xc(const int* __restrict__ tok,
                                            const float* __restrict__ emb,
                                            const float* __restrict__ c,
                                            float* __restrict__ xc)
{
    const int b = blockIdx.x, t = threadIdx.x;
    const int tk = tok[b];
    float4* x4 = (float4*)(xc + (size_t)b * (E_ + H_));
    x4[t]       = ((const float4*)(emb + (size_t)tk * E_))[t];
    x4[256 + t] = ((const float4*)(c + (size_t)b * H_))[t];
}

// ---------------------------------------------------------------------------
// GEMM with packed fma.rn.f32x2: C[b,n] = A[b,:K].W[n,:K] (+bias)
// block(128): 16(tx, 4n each) x 8(ty, 8b each). Accumulators are f32x2 pairs
// along b. As stride 68 (pair-aligned pad), Ws stride 66 (scalar pad).
// blockIdx.y = K-split; partial rows at blockIdx.y*64 + b.
// ---------------------------------------------------------------------------
__global__ __launch_bounds__(128) void k_gemm64(const float* __restrict__ A,
                                                const float* __restrict__ W,
                                                const float* __restrict__ bias,
                                                float* __restrict__ C,
                                                int K, int ldc, int klen)
{
    __shared__ float As[32 * 68];
    __shared__ float Ws[32 * 66];
    const int tid = threadIdx.x;
    const int tx = tid & 15;
    const int ty = tid >> 4;
    const int n0 = blockIdx.x * 64;
    const int kbase = blockIdx.y * klen;
    const int aoff = ty * 8 + ((ty >= 4) ? 2 : 0);      // always even
    const int woff = tx * 4 + ((tx >= 8) ? 1 : 0);

    unsigned long long accp[4][4];
#pragma unroll
    for (int ip = 0; ip < 4; ip++)
#pragma unroll
        for (int j = 0; j < 4; j++) accp[ip][j] = 0ull;

    for (int kc = 0; kc < klen; kc += 32) {
        __syncthreads();
#pragma unroll
        for (int p = 0; p < 4; p++) {
            const int id = tid + p * 128;
            const int row = id >> 3;
            const int c4 = (id & 7) << 2;
            const int roffA = row + ((row >> 5) << 1);
            const int roffW = row + (row >> 5);
            float4 av = *(const float4*)(A + (size_t)row * K + kbase + kc + c4);
            As[(c4 + 0) * 68 + roffA] = av.x;
            As[(c4 + 1) * 68 + roffA] = av.y;
            As[(c4 + 2) * 68 + roffA] = av.z;
            As[(c4 + 3) * 68 + roffA] = av.w;
            float4 wv = *(const float4*)(W + (size_t)(n0 + row) * K + kbase + kc + c4);
            Ws[(c4 + 0) * 66 + roffW] = wv.x;
            Ws[(c4 + 1) * 66 + roffW] = wv.y;
            Ws[(c4 + 2) * 66 + roffW] = wv.z;
            Ws[(c4 + 3) * 66 + roffW] = wv.w;
        }
        __syncthreads();
#pragma unroll 4
        for (int kk = 0; kk < 32; kk++) {
            const float* wrow = &Ws[kk * 66 + woff];
            unsigned long long wp[4];
#pragma unroll
            for (int j = 0; j < 4; j++) {
                float w = wrow[j];
                asm("mov.b64 %0, {%1, %1};" : "=l"(wp[j]) : "f"(w));
            }
            const float* arow = &As[kk * 68 + aoff];
            unsigned long long ap[4];
#pragma unroll
            for (int ip = 0; ip < 4; ip++)
                ap[ip] = *(const unsigned long long*)(arow + 2 * ip);
#pragma unroll
            for (int ip = 0; ip < 4; ip++)
#pragma unroll
                for (int j = 0; j < 4; j++)
                    asm("fma.rn.f32x2 %0, %1, %2, %0;"
                        : "+l"(accp[ip][j]) : "l"(ap[ip]), "l"(wp[j]));
        }
    }
    float b0 = 0.f, b1 = 0.f, b2 = 0.f, b3 = 0.f;
    if (bias) {
        b0 = bias[n0 + tx * 4 + 0];
        b1 = bias[n0 + tx * 4 + 1];
        b2 = bias[n0 + tx * 4 + 2];
        b3 = bias[n0 + tx * 4 + 3];
    }
#pragma unroll
    for (int ip = 0; ip < 4; ip++) {
        float lo[4], hi[4];
#pragma unroll
        for (int j = 0; j < 4; j++)
            asm("mov.b64 {%0, %1}, %2;" : "=f"(lo[j]), "=f"(hi[j]) : "l"(accp[ip][j]));
        const size_t row0 = (size_t)(blockIdx.y * 64 + ty * 8 + 2 * ip);
        *(float4*)(C + row0 * ldc + n0 + tx * 4) =
            make_float4(lo[0] + b0, lo[1] + b1, lo[2] + b2, lo[3] + b3);
        *(float4*)(C + (row0 + 1) * ldc + n0 + tx * 4) =
            make_float4(hi[0] + b0, hi[1] + b1, hi[2] + b2, hi[3] + b3);
    }
}

// ---------------------------------------------------------------------------
// gates: merge K-split partials, GRU nonlinearity, write h_new
// ---------------------------------------------------------------------------
__global__ __launch_bounds__(256) void k_gates(const float* __restrict__ gip,
                                               const float* __restrict__ ghp,
                                               const float* __restrict__ b_ih,
                                               const float* __restrict__ b_hh,
                                               const float* __restrict__ h_last,
                                               float* __restrict__ h_new)
{
    const int idx = blockIdx.x * blockDim.x + threadIdx.x;
    const int b = idx >> 10;
    const int h = idx & 1023;
    float ir = 0.f, iz = 0.f, in_ = 0.f;
#pragma unroll
    for (int sp = 0; sp < 4; sp++) {
        const float* g = gip + (size_t)(sp * B_ + b) * (3 * H_);
        ir += g[h];
        iz += g[h + H_];
        in_ += g[h + 2 * H_];
    }
    float hr = 0.f, hz = 0.f, hn = 0.f;
#pragma unroll
    for (int sp = 0; sp < 2; sp++) {
        const float* g = ghp + (size_t)(sp * B_ + b) * (3 * H_);
        hr += g[h];
        hz += g[h + H_];
        hn += g[h + 2 * H_];
    }
    ir += b_ih[h];           hr += b_hh[h];
    iz += b_ih[h + H_];      hz += b_hh[h + H_];
    in_ += b_ih[h + 2 * H_]; hn += b_hh[h + 2 * H_];
    const float r = 1.f / (1.f + expf(-(ir + hr)));
    const float z = 1.f / (1.f + expf(-(iz + hz)));
    const float n = tanhf(in_ + r * hn);
    h_new[idx] = (1.f - z) * n + z * h_last[idx];
}

// ---------------------------------------------------------------------------
extern "C" void kernel_launch(void* const* d_in, const int* in_sizes, int n_in,
                              void* d_out, int out_size)
{
    (void)in_sizes; (void)n_in; (void)out_size;
    const int* dec_input = (const int*)d_in[0];
    const float* dec_hidden = (const float*)d_in[1];
    const float* enc = (const float*)d_in[2];
    const float* emb = (const float*)d_in[3];
    const float* Wa1 = (const float*)d_in[4];
    const float* Wa2 = (const float*)d_in[5];
    const float* W_ih = (const float*)d_in[6];
    const float* W_hh = (const float*)d_in[7];
    const float* b_ih = (const float*)d_in[8];
    const float* b_hh = (const float*)d_in[9];
    const float* W_out = (const float*)d_in[10];
    const float* b_out = (const float*)d_in[11];

    float* out = (float*)d_out;
    float* logits = out;
    float* h_new = out + (size_t)B_ * V_;

    float* scratch = nullptr;
    cudaGetSymbolAddress((void**)&scratch, g_scratch);
    float* hWa1 = scratch + OFF_HWA1;
    float* e = scratch + OFF_E;
    float* c = scratch + OFF_C;
    float* xc = scratch + OFF_XC;
    float* gip = scratch + OFF_GIP;
    float* ghp = scratch + OFF_GHP;
    float* cp = scratch + OFF_CP;

    // attention
    k_hWa1<<<B_, 256>>>(dec_hidden, Wa1, hWa1);
    k_scores<<<(S_ * B_) / 32, 256>>>(enc, Wa1, Wa2, hWa1, e);
    k_softmax<<<B_, 256>>>(e);
    k_context_part<<<dim3(2, B_, NSPLIT), 128>>>(e, enc, cp);
    k_context_reduce<<<B_ * H_ / 4 / 256, 256>>>(cp, c);

    // GRU inputs
    k_xc<<<B_, 256>>>(dec_input, emb, c, xc);
    k_gemm64<<<dim3(48, 2), 128>>>(dec_hidden, W_hh, nullptr, ghp, H_, 3 * H_, 512);
    k_gemm64<<<dim3(48, 4), 128>>>(xc, W_ih, nullptr, gip, E_ + H_, 3 * H_, 512);
    k_gates<<<(B_ * H_) / 256, 256>>>(gip, ghp, b_ih, b_hh, dec_hidden, h_new);

    // logits = h_new @ W_out.T + b_out
    k_gemm64<<<dim3(V_ / 64, 1), 128>>>(h_new, W_out, b_out, logits, H_, V_, H_);
}

// round 3
// speedup vs baseline: 1.5552x; 1.2014x over previous
#include <cuda_runtime.h>
#include <cuda_bf16.h>
#include <math.h>
#include <stdint.h>

// Problem dims
#define V_ 32000
#define E_ 1024
#define H_ 1024
#define A_ 10
#define S_ 512
#define B_ 64

#define NSPLIT 16

// Scratch layout (floats)
#define OFF_HWA1 0            // B*A = 640
#define OFF_E    1024         // S*B = 32768
#define OFF_C    36864        // B*H = 65536
#define OFF_XC   102400       // B*(E+H) = 131072
#define OFF_GIP  233472       // 4*B*3H = 786432
#define OFF_GHP  1019904      // 2*B*3H = 393216
#define OFF_CP   1413120      // NSPLIT*B*H = 1048576
#define OFF_AHI  2461696      // B*H bf16 = 32768 floats
#define OFF_ALO  2494464      // B*H bf16 = 32768 floats
#define SCRATCH_FLOATS 2527232

__device__ float g_scratch[SCRATCH_FLOATS];

// ---------------------------------------------------------------------------
// hWa1[b][a] = sum_h h_last[b,h] * Wa1[a,h]
// ---------------------------------------------------------------------------
__global__ __launch_bounds__(256) void k_hWa1(const float* __restrict__ h,
                                              const float* __restrict__ Wa1,
                                              float* __restrict__ hWa1)
{
    const int b = blockIdx.x;
    const int tid = threadIdx.x;
    float4 hv = ((const float4*)(h + (size_t)b * H_))[tid];
    float p[A_];
#pragma unroll
    for (int a = 0; a < A_; a++) {
        float4 w = ((const float4*)(Wa1 + (size_t)a * (2 * H_)))[tid];
        p[a] = hv.x * w.x + hv.y * w.y + hv.z * w.z + hv.w * w.w;
    }
    __shared__ float red[8][A_];
    const int lane = tid & 31, wid = tid >> 5;
#pragma unroll
    for (int a = 0; a < A_; a++) {
        float v = p[a];
        v += __shfl_xor_sync(0xffffffffu, v, 16);
        v += __shfl_xor_sync(0xffffffffu, v, 8);
        v += __shfl_xor_sync(0xffffffffu, v, 4);
        v += __shfl_xor_sync(0xffffffffu, v, 2);
        v += __shfl_xor_sync(0xffffffffu, v, 1);
        if (lane == 0) red[wid][a] = v;
    }
    __syncthreads();
    if (tid < A_) {
        float s = 0.f;
#pragma unroll
        for (int w = 0; w < 8; w++) s += red[w][tid];
        hWa1[b * A_ + tid] = s;
    }
}

// ---------------------------------------------------------------------------
// scores: e[r] = sum_a Wa2[a]*tanh(hWa1[b][a] + enc[r,:].Wa1[a,H:])
// ---------------------------------------------------------------------------
__global__ __launch_bounds__(256) void k_scores(const float* __restrict__ enc,
                                                const float* __restrict__ Wa1,
                                                const float* __restrict__ Wa2,
                                                const float* __restrict__ hWa1,
                                                float* __restrict__ e_out)
{
    __shared__ float Wsh[A_ * H_];   // 40KB
    const int tid = threadIdx.x;
    for (int id = tid; id < A_ * (H_ / 4); id += 256) {
        int a = id >> 8;
        int c4 = id & 255;
        ((float4*)Wsh)[a * 256 + c4] =
            *(const float4*)(Wa1 + (size_t)a * (2 * H_) + H_ + (c4 << 2));
    }
    __syncthreads();

    const int lane = tid & 31, wid = tid >> 5;
    const size_t r0 = (size_t)blockIdx.x * 32 + wid * 4;
    const float4* e4 = (const float4*)enc;

    float acc0[A_], acc1[A_], acc2[A_], acc3[A_];
#pragma unroll
    for (int a = 0; a < A_; a++) { acc0[a] = 0.f; acc1[a] = 0.f; acc2[a] = 0.f; acc3[a] = 0.f; }

#pragma unroll
    for (int it = 0; it < 8; it++) {
        const int h4 = it * 32 + lane;
        float4 x0 = e4[(r0 + 0) * 256 + h4];
        float4 x1 = e4[(r0 + 1) * 256 + h4];
        float4 x2 = e4[(r0 + 2) * 256 + h4];
        float4 x3 = e4[(r0 + 3) * 256 + h4];
#pragma unroll
        for (int a = 0; a < A_; a++) {
            float4 w = ((const float4*)Wsh)[a * 256 + h4];
            acc0[a] += x0.x * w.x + x0.y * w.y + x0.z * w.z + x0.w * w.w;
            acc1[a] += x1.x * w.x + x1.y * w.y + x1.z * w.z + x1.w * w.w;
            acc2[a] += x2.x * w.x + x2.y * w.y + x2.z * w.z + x2.w * w.w;
            acc3[a] += x3.x * w.x + x3.y * w.y + x3.z * w.z + x3.w * w.w;
        }
    }
#pragma unroll
    for (int a = 0; a < A_; a++) {
        float v;
        v = acc0[a];
        v += __shfl_xor_sync(0xffffffffu, v, 16); v += __shfl_xor_sync(0xffffffffu, v, 8);
        v += __shfl_xor_sync(0xffffffffu, v, 4);  v += __shfl_xor_sync(0xffffffffu, v, 2);
        v += __shfl_xor_sync(0xffffffffu, v, 1);  acc0[a] = v;
        v = acc1[a];
        v += __shfl_xor_sync(0xffffffffu, v, 16); v += __shfl_xor_sync(0xffffffffu, v, 8);
        v += __shfl_xor_sync(0xffffffffu, v, 4);  v += __shfl_xor_sync(0xffffffffu, v, 2);
        v += __shfl_xor_sync(0xffffffffu, v, 1);  acc1[a] = v;
        v = acc2[a];
        v += __shfl_xor_sync(0xffffffffu, v, 16); v += __shfl_xor_sync(0xffffffffu, v, 8);
        v += __shfl_xor_sync(0xffffffffu, v, 4);  v += __shfl_xor_sync(0xffffffffu, v, 2);
        v += __shfl_xor_sync(0xffffffffu, v, 1);  acc2[a] = v;
        v = acc3[a];
        v += __shfl_xor_sync(0xffffffffu, v, 16); v += __shfl_xor_sync(0xffffffffu, v, 8);
        v += __shfl_xor_sync(0xffffffffu, v, 4);  v += __shfl_xor_sync(0xffffffffu, v, 2);
        v += __shfl_xor_sync(0xffffffffu, v, 1);  acc3[a] = v;
    }
    float tsum[A_];
#pragma unroll
    for (int a = 0; a < A_; a++) {
        float t = acc0[a];
        if (lane == 1) t = acc1[a];
        if (lane == 2) t = acc2[a];
        if (lane == 3) t = acc3[a];
        tsum[a] = t;
    }
    if (lane < 4) {
        const size_t r = r0 + lane;
        const int b = (int)(r & (B_ - 1));
        float ev = 0.f;
#pragma unroll
        for (int a = 0; a < A_; a++)
            ev += Wa2[a] * tanhf(hWa1[b * A_ + a] + tsum[a]);
        e_out[r] = ev;
    }
}

// ---------------------------------------------------------------------------
// softmax over s (axis 0) per b, in place
// ---------------------------------------------------------------------------
__global__ __launch_bounds__(256) void k_softmax(float* __restrict__ e)
{
    const int b = blockIdx.x, tid = threadIdx.x;
    __shared__ float red[256];
    float v0 = e[(size_t)tid * B_ + b];
    float v1 = e[(size_t)(tid + 256) * B_ + b];
    red[tid] = fmaxf(v0, v1);
    __syncthreads();
    for (int s = 128; s > 0; s >>= 1) {
        if (tid < s) red[tid] = fmaxf(red[tid], red[tid + s]);
        __syncthreads();
    }
    const float M = red[0];
    __syncthreads();
    float e0 = expf(v0 - M), e1 = expf(v1 - M);
    red[tid] = e0 + e1;
    __syncthreads();
    for (int s = 128; s > 0; s >>= 1) {
        if (tid < s) red[tid] += red[tid + s];
        __syncthreads();
    }
    const float inv = 1.f / red[0];
    e[(size_t)tid * B_ + b] = e0 * inv;
    e[(size_t)(tid + 256) * B_ + b] = e1 * inv;
}

// ---------------------------------------------------------------------------
// context partials: cp[sp][b][h] = sum_{s in split sp} alpha[s,b]*enc[s,b,h]
// grid(2, B, NSPLIT), block(128)
// ---------------------------------------------------------------------------
__global__ __launch_bounds__(128) void k_context_part(const float* __restrict__ alpha,
                                                      const float* __restrict__ enc,
                                                      float* __restrict__ cp)
{
    const int b = blockIdx.y;
    const int sp = blockIdx.z;
    const int h0 = blockIdx.x * 512 + threadIdx.x * 4;
    __shared__ float al[S_ / NSPLIT];
    if (threadIdx.x < S_ / NSPLIT)
        al[threadIdx.x] = alpha[(size_t)(sp * (S_ / NSPLIT) + threadIdx.x) * B_ + b];
    __syncthreads();
    float4 acc = make_float4(0.f, 0.f, 0.f, 0.f);
    const float* base = enc + (size_t)(sp * (S_ / NSPLIT)) * B_ * H_ + (size_t)b * H_ + h0;
#pragma unroll
    for (int s = 0; s < S_ / NSPLIT; s++) {
        float4 v = *(const float4*)(base + (size_t)s * (B_ * H_));
        float a = al[s];
        acc.x += a * v.x; acc.y += a * v.y; acc.z += a * v.z; acc.w += a * v.w;
    }
    *(float4*)(cp + ((size_t)sp * B_ + b) * H_ + h0) = acc;
}

// ---------------------------------------------------------------------------
// reduce context partials: c = sum_sp cp[sp]
// ---------------------------------------------------------------------------
__global__ __launch_bounds__(256) void k_context_reduce(const float* __restrict__ cp,
                                                        float* __restrict__ c)
{
    const int idx = blockIdx.x * 256 + threadIdx.x;
    float4 acc = make_float4(0.f, 0.f, 0.f, 0.f);
#pragma unroll
    for (int sp = 0; sp < NSPLIT; sp++) {
        float4 v = ((const float4*)cp)[(size_t)sp * (B_ * H_ / 4) + idx];
        acc.x += v.x; acc.y += v.y; acc.z += v.z; acc.w += v.w;
    }
    ((float4*)c)[idx] = acc;
}

// ---------------------------------------------------------------------------
// xc[b,:] = [ emb[tok[b], :E] ; c[b, :H] ]
// ---------------------------------------------------------------------------
__global__ __launch_bounds__(256) void k_xc(const int* __restrict__ tok,
                                            const float* __restrict__ emb,
                                            const float* __restrict__ c,
                                            float* __restrict__ xc)
{
    const int b = blockIdx.x, t = threadIdx.x;
    const int tk = tok[b];
    float4* x4 = (float4*)(xc + (size_t)b * (E_ + H_));
    x4[t]       = ((const float4*)(emb + (size_t)tk * E_))[t];
    x4[256 + t] = ((const float4*)(c + (size_t)b * H_))[t];
}

// ---------------------------------------------------------------------------
// fp32x2 GEMM (gi/gh): C[b,n] = A[b,:K].W[n,:K], K-split partials
// ---------------------------------------------------------------------------
__global__ __launch_bounds__(128) void k_gemm64(const float* __restrict__ A,
                                                const float* __restrict__ W,
                                                const float* __restrict__ bias,
                                                float* __restrict__ C,
                                                int K, int ldc, int klen)
{
    __shared__ float As[32 * 68];
    __shared__ float Ws[32 * 66];
    const int tid = threadIdx.x;
    const int tx = tid & 15;
    const int ty = tid >> 4;
    const int n0 = blockIdx.x * 64;
    const int kbase = blockIdx.y * klen;
    const int aoff = ty * 8 + ((ty >= 4) ? 2 : 0);
    const int woff = tx * 4 + ((tx >= 8) ? 1 : 0);

    unsigned long long accp[4][4];
#pragma unroll
    for (int ip = 0; ip < 4; ip++)
#pragma unroll
        for (int j = 0; j < 4; j++) accp[ip][j] = 0ull;

    for (int kc = 0; kc < klen; kc += 32) {
        __syncthreads();
#pragma unroll
        for (int p = 0; p < 4; p++) {
            const int id = tid + p * 128;
            const int row = id >> 3;
            const int c4 = (id & 7) << 2;
            const int roffA = row + ((row >> 5) << 1);
            const int roffW = row + (row >> 5);
            float4 av = *(const float4*)(A + (size_t)row * K + kbase + kc + c4);
            As[(c4 + 0) * 68 + roffA] = av.x;
            As[(c4 + 1) * 68 + roffA] = av.y;
            As[(c4 + 2) * 68 + roffA] = av.z;
            As[(c4 + 3) * 68 + roffA] = av.w;
            float4 wv = *(const float4*)(W + (size_t)(n0 + row) * K + kbase + kc + c4);
            Ws[(c4 + 0) * 66 + roffW] = wv.x;
            Ws[(c4 + 1) * 66 + roffW] = wv.y;
            Ws[(c4 + 2) * 66 + roffW] = wv.z;
            Ws[(c4 + 3) * 66 + roffW] = wv.w;
        }
        __syncthreads();
#pragma unroll 4
        for (int kk = 0; kk < 32; kk++) {
            const float* wrow = &Ws[kk * 66 + woff];
            unsigned long long wp[4];
#pragma unroll
            for (int j = 0; j < 4; j++) {
                float w = wrow[j];
                asm("mov.b64 %0, {%1, %1};" : "=l"(wp[j]) : "f"(w));
            }
            const float* arow = &As[kk * 68 + aoff];
            unsigned long long ap[4];
#pragma unroll
            for (int ip = 0; ip < 4; ip++)
                ap[ip] = *(const unsigned long long*)(arow + 2 * ip);
#pragma unroll
            for (int ip = 0; ip < 4; ip++)
#pragma unroll
                for (int j = 0; j < 4; j++)
                    asm("fma.rn.f32x2 %0, %1, %2, %0;"
                        : "+l"(accp[ip][j]) : "l"(ap[ip]), "l"(wp[j]));
        }
    }
    float b0 = 0.f, b1 = 0.f, b2 = 0.f, b3 = 0.f;
    if (bias) {
        b0 = bias[n0 + tx * 4 + 0];
        b1 = bias[n0 + tx * 4 + 1];
        b2 = bias[n0 + tx * 4 + 2];
        b3 = bias[n0 + tx * 4 + 3];
    }
#pragma unroll
    for (int ip = 0; ip < 4; ip++) {
        float lo[4], hi[4];
#pragma unroll
        for (int j = 0; j < 4; j++)
            asm("mov.b64 {%0, %1}, %2;" : "=f"(lo[j]), "=f"(hi[j]) : "l"(accp[ip][j]));
        const size_t row0 = (size_t)(blockIdx.y * 64 + ty * 8 + 2 * ip);
        *(float4*)(C + row0 * ldc + n0 + tx * 4) =
            make_float4(lo[0] + b0, lo[1] + b1, lo[2] + b2, lo[3] + b3);
        *(float4*)(C + (row0 + 1) * ldc + n0 + tx * 4) =
            make_float4(hi[0] + b0, hi[1] + b1, hi[2] + b2, hi[3] + b3);
    }
}

// ---------------------------------------------------------------------------
// gates: merge K-split partials, GRU nonlinearity, write h_new
// ---------------------------------------------------------------------------
__global__ __launch_bounds__(256) void k_gates(const float* __restrict__ gip,
                                               const float* __restrict__ ghp,
                                               const float* __restrict__ b_ih,
                                               const float* __restrict__ b_hh,
                                               const float* __restrict__ h_last,
                                               float* __restrict__ h_new)
{
    const int idx = blockIdx.x * blockDim.x + threadIdx.x;
    const int b = idx >> 10;
    const int h = idx & 1023;
    float ir = 0.f, iz = 0.f, in_ = 0.f;
#pragma unroll
    for (int sp = 0; sp < 4; sp++) {
        const float* g = gip + (size_t)(sp * B_ + b) * (3 * H_);
        ir += g[h];
        iz += g[h + H_];
        in_ += g[h + 2 * H_];
    }
    float hr = 0.f, hz = 0.f, hn = 0.f;
#pragma unroll
    for (int sp = 0; sp < 2; sp++) {
        const float* g = ghp + (size_t)(sp * B_ + b) * (3 * H_);
        hr += g[h];
        hz += g[h + H_];
        hn += g[h + 2 * H_];
    }
    ir += b_ih[h];           hr += b_hh[h];
    iz += b_ih[h + H_];      hz += b_hh[h + H_];
    in_ += b_ih[h + 2 * H_]; hn += b_hh[h + 2 * H_];
    const float r = 1.f / (1.f + expf(-(ir + hr)));
    const float z = 1.f / (1.f + expf(-(iz + hz)));
    const float n = tanhf(in_ + r * hn);
    h_new[idx] = (1.f - z) * n + z * h_last[idx];
}

// ---------------------------------------------------------------------------
// split fp32 -> bf16 (hi) + bf16 (residual lo)
// ---------------------------------------------------------------------------
__device__ __forceinline__ void cvt_hilo2(float f0, float f1,
                                          uint32_t& hp, uint32_t& lp)
{
    __nv_bfloat162 h2 = __floats2bfloat162_rn(f0, f1);
    float b0 = __bfloat162float(__low2bfloat16(h2));
    float b1 = __bfloat162float(__high2bfloat16(h2));
    __nv_bfloat162 l2 = __floats2bfloat162_rn(f0 - b0, f1 - b1);
    hp = *reinterpret_cast<uint32_t*>(&h2);
    lp = *reinterpret_cast<uint32_t*>(&l2);
}

// pre-convert h_new (64x1024) into bf16 hi/lo arrays
__global__ __launch_bounds__(256) void k_cvtA(const float* __restrict__ h,
                                              uint32_t* __restrict__ Ah,   // as bf16x2
                                              uint32_t* __restrict__ Al)
{
    const int i = blockIdx.x * 256 + threadIdx.x;   // 0..16383 (float4 units)
    float4 v = ((const float4*)h)[i];
    uint32_t h01, h23, l01, l23;
    cvt_hilo2(v.x, v.y, h01, l01);
    cvt_hilo2(v.z, v.w, h23, l23);
    ((uint2*)Ah)[i] = make_uint2(h01, h23);
    ((uint2*)Al)[i] = make_uint2(l01, l23);
}

#define MMA_BF16(d, a0, a1, a2, a3, b0, b1)                                   \
    asm volatile("mma.sync.aligned.m16n8k16.row.col.f32.bf16.bf16.f32 "       \
                 "{%0,%1,%2,%3}, {%4,%5,%6,%7}, {%8,%9}, {%0,%1,%2,%3};"      \
                 : "+f"(d[0]), "+f"(d[1]), "+f"(d[2]), "+f"(d[3])             \
                 : "r"(a0), "r"(a1), "r"(a2), "r"(a3), "r"(b0), "r"(b1))

// ---------------------------------------------------------------------------
// logits GEMM via bf16 tensor cores, 3-term split precision.
// C[64,32000] = A[64,1024] . W[32000,1024]^T + bias
// grid(250), block(128)=4 warps; warp tile m64 x n32; k-chunk 32.
// Single smem buffer; LDG prefetch of next chunk overlaps compute.
// ---------------------------------------------------------------------------
#define SSTR 40   // smem row stride in bf16 elems (80B: 16B-aligned, conflict-free)

__global__ __launch_bounds__(128) void k_logits_mma(
    const __nv_bfloat16* __restrict__ Ah, const __nv_bfloat16* __restrict__ Al,
    const float* __restrict__ W, const float* __restrict__ bias,
    float* __restrict__ C)
{
    __shared__ __align__(16) __nv_bfloat16 Wh[128][SSTR];
    __shared__ __align__(16) __nv_bfloat16 Wl[128][SSTR];
    __shared__ __align__(16) __nv_bfloat16 Ash[64][SSTR];
    __shared__ __align__(16) __nv_bfloat16 Asl[64][SSTR];

    const int tid = threadIdx.x;
    const int wid = tid >> 5, lane = tid & 31;
    const int g = lane >> 2, tg = lane & 3;
    const int n0B = blockIdx.x * 128;

    const int wrow = tid;              // W row handled by this thread (0..127)
    const int arow = tid >> 1;         // A row (0..63)
    const int ak0 = (tid & 1) * 16;    // A k offset (16 bf16 = 32B)

    float acc[4][4][4];
#pragma unroll
    for (int mt = 0; mt < 4; mt++)
#pragma unroll
        for (int nt = 0; nt < 4; nt++)
#pragma unroll
            for (int q = 0; q < 4; q++) acc[mt][nt][q] = 0.f;

    const float* wptr = W + (size_t)(n0B + wrow) * 1024;
    const __nv_bfloat16* ahp = Ah + arow * 1024 + ak0;
    const __nv_bfloat16* alp = Al + arow * 1024 + ak0;

    // prefetch chunk 0
    float4 w4[8];
    uint4 a4[4];
#pragma unroll
    for (int q = 0; q < 8; q++) w4[q] = *(const float4*)(wptr + q * 4);
    a4[0] = *(const uint4*)(ahp);
    a4[1] = *(const uint4*)(ahp + 8);
    a4[2] = *(const uint4*)(alp);
    a4[3] = *(const uint4*)(alp + 8);

    for (int ch = 0; ch < 32; ch++) {
        __syncthreads();   // previous chunk fully consumed
        // convert + store W chunk (this thread's row: 32 floats)
        {
            uint32_t hp[16], lp[16];
#pragma unroll
            for (int q = 0; q < 8; q++) {
                cvt_hilo2(w4[q].x, w4[q].y, hp[2 * q], lp[2 * q]);
                cvt_hilo2(w4[q].z, w4[q].w, hp[2 * q + 1], lp[2 * q + 1]);
            }
#pragma unroll
            for (int s = 0; s < 4; s++) {
                *(uint4*)&Wh[wrow][s * 8] =
                    make_uint4(hp[4 * s], hp[4 * s + 1], hp[4 * s + 2], hp[4 * s + 3]);
                *(uint4*)&Wl[wrow][s * 8] =
                    make_uint4(lp[4 * s], lp[4 * s + 1], lp[4 * s + 2], lp[4 * s + 3]);
            }
            *(uint4*)&Ash[arow][ak0] = a4[0];
            *(uint4*)&Ash[arow][ak0 + 8] = a4[1];
            *(uint4*)&Asl[arow][ak0] = a4[2];
            *(uint4*)&Asl[arow][ak0 + 8] = a4[3];
        }
        __syncthreads();   // chunk visible
        // prefetch next chunk (overlaps compute below)
        if (ch < 31) {
            const float* wp2 = wptr + (ch + 1) * 32;
#pragma unroll
            for (int q = 0; q < 8; q++) w4[q] = *(const float4*)(wp2 + q * 4);
            a4[0] = *(const uint4*)(ahp + (ch + 1) * 32);
            a4[1] = *(const uint4*)(ahp + (ch + 1) * 32 + 8);
            a4[2] = *(const uint4*)(alp + (ch + 1) * 32);
            a4[3] = *(const uint4*)(alp + (ch + 1) * 32 + 8);
        }
        // compute: 2 k16 steps
#pragma unroll
        for (int ks = 0; ks < 2; ks++) {
            const int k0 = ks * 16;
            uint32_t bh[4][2], bl[4][2];
#pragma unroll
            for (int nt = 0; nt < 4; nt++) {
                const int r = wid * 32 + nt * 8 + g;
                bh[nt][0] = *(const uint32_t*)&Wh[r][k0 + 2 * tg];
                bh[nt][1] = *(const uint32_t*)&Wh[r][k0 + 2 * tg + 8];
                bl[nt][0] = *(const uint32_t*)&Wl[r][k0 + 2 * tg];
                bl[nt][1] = *(const uint32_t*)&Wl[r][k0 + 2 * tg + 8];
            }
#pragma unroll
            for (int mt = 0; mt < 4; mt++) {
                const int r0 = mt * 16 + g;
                uint32_t ah0 = *(const uint32_t*)&Ash[r0][k0 + 2 * tg];
                uint32_t ah1 = *(const uint32_t*)&Ash[r0 + 8][k0 + 2 * tg];
                uint32_t ah2 = *(const uint32_t*)&Ash[r0][k0 + 2 * tg + 8];
                uint32_t ah3 = *(const uint32_t*)&Ash[r0 + 8][k0 + 2 * tg + 8];
                uint32_t al0 = *(const uint32_t*)&Asl[r0][k0 + 2 * tg];
                uint32_t al1 = *(const uint32_t*)&Asl[r0 + 8][k0 + 2 * tg];
                uint32_t al2 = *(const uint32_t*)&Asl[r0][k0 + 2 * tg + 8];
                uint32_t al3 = *(const uint32_t*)&Asl[r0 + 8][k0 + 2 * tg + 8];
#pragma unroll
                for (int nt = 0; nt < 4; nt++) {
                    MMA_BF16(acc[mt][nt], ah0, ah1, ah2, ah3, bh[nt][0], bh[nt][1]);
                    MMA_BF16(acc[mt][nt], al0, al1, al2, al3, bh[nt][0], bh[nt][1]);
                    MMA_BF16(acc[mt][nt], ah0, ah1, ah2, ah3, bl[nt][0], bl[nt][1]);
                }
            }
        }
    }
    // epilogue: bias + store
#pragma unroll
    for (int mt = 0; mt < 4; mt++) {
        const int r0 = mt * 16 + g;
#pragma unroll
        for (int nt = 0; nt < 4; nt++) {
            const int col = n0B + wid * 32 + nt * 8 + 2 * tg;
            float2 bb = *(const float2*)(bias + col);
            *(float2*)(C + (size_t)r0 * V_ + col) =
                make_float2(acc[mt][nt][0] + bb.x, acc[mt][nt][1] + bb.y);
            *(float2*)(C + (size_t)(r0 + 8) * V_ + col) =
                make_float2(acc[mt][nt][2] + bb.x, acc[mt][nt][3] + bb.y);
        }
    }
}

// ---------------------------------------------------------------------------
extern "C" void kernel_launch(void* const* d_in, const int* in_sizes, int n_in,
                              void* d_out, int out_size)
{
    (void)in_sizes; (void)n_in; (void)out_size;
    const int* dec_input = (const int*)d_in[0];
    const float* dec_hidden = (const float*)d_in[1];
    const float* enc = (const float*)d_in[2];
    const float* emb = (const float*)d_in[3];
    const float* Wa1 = (const float*)d_in[4];
    const float* Wa2 = (const float*)d_in[5];
    const float* W_ih = (const float*)d_in[6];
    const float* W_hh = (const float*)d_in[7];
    const float* b_ih = (const float*)d_in[8];
    const float* b_hh = (const float*)d_in[9];
    const float* W_out = (const float*)d_in[10];
    const float* b_out = (const float*)d_in[11];

    float* out = (float*)d_out;
    float* logits = out;
    float* h_new = out + (size_t)B_ * V_;

    float* scratch = nullptr;
    cudaGetSymbolAddress((void**)&scratch, g_scratch);
    float* hWa1 = scratch + OFF_HWA1;
    float* e = scratch + OFF_E;
    float* c = scratch + OFF_C;
    float* xc = scratch + OFF_XC;
    float* gip = scratch + OFF_GIP;
    float* ghp = scratch + OFF_GHP;
    float* cp = scratch + OFF_CP;
    uint32_t* Ah = (uint32_t*)(scratch + OFF_AHI);
    uint32_t* Al = (uint32_t*)(scratch + OFF_ALO);

    // attention
    k_hWa1<<<B_, 256>>>(dec_hidden, Wa1, hWa1);
    k_scores<<<(S_ * B_) / 32, 256>>>(enc, Wa1, Wa2, hWa1, e);
    k_softmax<<<B_, 256>>>(e);
    k_context_part<<<dim3(2, B_, NSPLIT), 128>>>(e, enc, cp);
    k_context_reduce<<<B_ * H_ / 4 / 256, 256>>>(cp, c);

    // GRU
    k_xc<<<B_, 256>>>(dec_input, emb, c, xc);
    k_gemm64<<<dim3(48, 2), 128>>>(dec_hidden, W_hh, nullptr, ghp, H_, 3 * H_, 512);
    k_gemm64<<<dim3(48, 4), 128>>>(xc, W_ih, nullptr, gip, E_ + H_, 3 * H_, 512);
    k_gates<<<(B_ * H_) / 256, 256>>>(gip, ghp, b_ih, b_hh, dec_hidden, h_new);

    // logits via bf16 tensor cores (split precision)
    k_cvtA<<<64, 256>>>(h_new, Ah, Al);
    k_logits_mma<<<V_ / 128, 128>>>((const __nv_bfloat16*)Ah, (const __nv_bfloat16*)Al,
                                    W_out, b_out, logits);
}